// round 3
// baseline (speedup 1.0000x reference)
#include <cuda_runtime.h>
#include <cuda_bf16.h>
#include <cstdint>

#define Tn   4096
#define Cn   512
#define Pn   64
#define PSn  16
#define CSn  5
#define MBn  128
#define FDn  128
#define Bn   2

// Scratch (device globals; no allocation allowed)
__device__ __align__(16) float g_wcomb[Cn * FDn];        // 256 KB: W_proj2 @ W_FINAL
__device__ __align__(16) float g_z[Bn * Tn * FDn];       // 4 MB:  y @ Wcomb
__device__ __align__(16) float g_yc[Bn * Tn * 8];        // 256 KB: y @ W_proj_comp, padded stride 8

// ---------------------------------------------------------------------------
// Kernel A: Wcomb[c][f] = sum_m W_proj2[c][m] * W_FINAL[m][f]
// grid 128, block 128; each block does 4 c-rows.
// ---------------------------------------------------------------------------
__global__ void wcomb_kernel(const float* __restrict__ Wp2,
                             const float* __restrict__ Wfin) {
    __shared__ float wp[4][MBn];
    const int tid = threadIdx.x;
    const int c0 = blockIdx.x * 4;
#pragma unroll
    for (int i = 0; i < 4; i++)
        wp[i][tid] = Wp2[(c0 + i) * MBn + tid];
    __syncthreads();
    float a0 = 0.f, a1 = 0.f, a2 = 0.f, a3 = 0.f;
#pragma unroll 8
    for (int m = 0; m < MBn; m++) {
        const float wf = Wfin[m * FDn + tid];
        a0 += wp[0][m] * wf;
        a1 += wp[1][m] * wf;
        a2 += wp[2][m] * wf;
        a3 += wp[3][m] * wf;
    }
    g_wcomb[(c0 + 0) * FDn + tid] = a0;
    g_wcomb[(c0 + 1) * FDn + tid] = a1;
    g_wcomb[(c0 + 2) * FDn + tid] = a2;
    g_wcomb[(c0 + 3) * FDn + tid] = a3;
}

// ---------------------------------------------------------------------------
// Kernel C: yc[b][t][k] = sum_c y[b][t][c] * W_proj_comp[c][k], k < 5
// stored with row stride 8 (32 B) so each later gather is exactly 1 L2 sector.
// grid (T/32, B), block 160: thread = (tt = tid/5, k = tid%5).
// ---------------------------------------------------------------------------
__global__ void yc_kernel(const float* __restrict__ y,
                          const float* __restrict__ Wpc) {
    const int b  = blockIdx.y;
    const int t  = blockIdx.x * 32 + threadIdx.x / 5;
    const int k  = threadIdx.x % 5;
    const float* yr = y + ((size_t)b * Tn + t) * Cn;
    float acc = 0.f;
#pragma unroll 8
    for (int c = 0; c < Cn; c++)
        acc += yr[c] * __ldg(Wpc + c * CSn + k);
    g_yc[((size_t)b * Tn + t) * 8 + k] = acc;
}

// ---------------------------------------------------------------------------
// Kernel B: z = y @ Wcomb   (B,T,512)@(512,128)
// grid (T/32, B), block 256. Tile: 32 t x 128 m, BK=16.
// Thread tile 2t x 8m (16 accumulators).
// ---------------------------------------------------------------------------
__global__ void z_kernel(const float* __restrict__ y) {
    __shared__ float  ys[32 * 16];        // [t][k]
    __shared__ float4 ws4[16 * 32];       // [k][m/4]
    const int b   = blockIdx.y;
    const int t0  = blockIdx.x * 32;
    const int tid = threadIdx.x;
    const int tx  = tid & 15;             // m group (8 m each)
    const int ty  = tid >> 4;             // t group (2 t each)

    float acc[2][8];
#pragma unroll
    for (int i = 0; i < 2; i++)
#pragma unroll
        for (int j = 0; j < 8; j++) acc[i][j] = 0.f;

    const float* yb = y + ((size_t)b * Tn + t0) * Cn;
    const float4* wc4 = (const float4*)g_wcomb;

    for (int c0 = 0; c0 < Cn; c0 += 16) {
        // load y tile: 512 floats
#pragma unroll
        for (int i = 0; i < 2; i++) {
            const int lin = tid + i * 256;          // 0..511
            ys[lin] = yb[(lin >> 4) * Cn + c0 + (lin & 15)];
        }
        // load W tile: 512 float4
#pragma unroll
        for (int i = 0; i < 2; i++) {
            const int lin = tid + i * 256;          // float4 index
            ws4[lin] = wc4[(c0 + (lin >> 5)) * 32 + (lin & 31)];
        }
        __syncthreads();
#pragma unroll
        for (int k = 0; k < 16; k++) {
            const float4 w0 = ws4[k * 32 + tx * 2];
            const float4 w1 = ws4[k * 32 + tx * 2 + 1];
#pragma unroll
            for (int i = 0; i < 2; i++) {
                const float yv = ys[(ty * 2 + i) * 16 + k];
                acc[i][0] += yv * w0.x; acc[i][1] += yv * w0.y;
                acc[i][2] += yv * w0.z; acc[i][3] += yv * w0.w;
                acc[i][4] += yv * w1.x; acc[i][5] += yv * w1.y;
                acc[i][6] += yv * w1.z; acc[i][7] += yv * w1.w;
            }
        }
        __syncthreads();
    }
    float4* zb = (float4*)(g_z + ((size_t)b * Tn + t0) * FDn);
#pragma unroll
    for (int i = 0; i < 2; i++) {
        zb[(ty * 2 + i) * 32 + tx * 2]     = make_float4(acc[i][0], acc[i][1], acc[i][2], acc[i][3]);
        zb[(ty * 2 + i) * 32 + tx * 2 + 1] = make_float4(acc[i][4], acc[i][5], acc[i][6], acc[i][7]);
    }
}

// ---------------------------------------------------------------------------
// Main fused kernel: one block per (b,t), 128 threads.
//   res[p]  = sum_{s,c} yc[b, patches[t,p,s], c] * W_BASE[p,s,c] + W_BIAS[p]
//   mix[q]  = sum_p res[p] * W_presoftmax1[p,q]
//   out[f]  = sum_p mix[p] * z[b, patches_proj[t,p], f]     (W_FINAL folded into z)
// ---------------------------------------------------------------------------
__global__ void __launch_bounds__(128)
main_kernel(const float* __restrict__ WBASE,
            const float* __restrict__ WBIAS,
            const float* __restrict__ Wpre,
            const int*   __restrict__ patches,
            const int*   __restrict__ pproj,
            float*       __restrict__ out) {
    const int b   = blockIdx.y;
    const int t   = blockIdx.x;
    const int tid = threadIdx.x;

    __shared__ float sred[128];
    __shared__ float sres[Pn];
    __shared__ float smix[Pn];
    __shared__ int   spp[Pn];

    // ---- res: thread (p = tid&63, half = tid>>6) covers 8 s-values ----
    {
        const int p    = tid & 63;
        const int half = tid >> 6;
        const int*   pat = patches + t * (Pn * PSn) + p * PSn + half * 8;
        const float* wb  = WBASE + p * (PSn * CSn) + half * 8 * CSn;
        const float* ycb = g_yc + (size_t)b * Tn * 8;
        float acc = 0.f;
#pragma unroll
        for (int s = 0; s < 8; s++) {
            const int idx = __ldg(pat + s);
            const float4 v = *(const float4*)(ycb + idx * 8);
            const float  v4 = __ldg(ycb + idx * 8 + 4);
            const float* w = wb + s * CSn;
            acc += v.x * w[0] + v.y * w[1] + v.z * w[2] + v.w * w[3] + v4 * w[4];
        }
        sred[tid] = acc;
    }
    if (tid >= 64) spp[tid - 64] = pproj[t * Pn + (tid - 64)];
    __syncthreads();
    if (tid < 64) sres[tid] = sred[tid] + sred[tid + 64] + WBIAS[tid];
    __syncthreads();
    // ---- mix ----
    if (tid < 64) {
        float m = 0.f;
#pragma unroll 8
        for (int p2 = 0; p2 < Pn; p2++)
            m += sres[p2] * __ldg(Wpre + p2 * Pn + tid);
        smix[tid] = m;
    }
    __syncthreads();
    // ---- final: gather z rows, weighted sum ----
    const float* zb = g_z + (size_t)b * Tn * FDn + tid;
    float o = 0.f;
#pragma unroll 16
    for (int p2 = 0; p2 < Pn; p2++)
        o += smix[p2] * __ldg(zb + spp[p2] * FDn);
    out[((size_t)b * Tn + t) * FDn + tid] = o;
}

// ---------------------------------------------------------------------------
extern "C" void kernel_launch(void* const* d_in, const int* in_sizes, int n_in,
                              void* d_out, int out_size) {
    const float* y     = (const float*)d_in[0];
    const float* WBASE = (const float*)d_in[1];
    const float* WBIAS = (const float*)d_in[2];
    const float* Wp2   = (const float*)d_in[3];
    const float* Wpc   = (const float*)d_in[4];
    const float* Wpre  = (const float*)d_in[5];
    const float* Wfin  = (const float*)d_in[6];
    const int*   patches = (const int*)d_in[7];
    const int*   pproj   = (const int*)d_in[8];
    float* out = (float*)d_out;

    wcomb_kernel<<<128, 128>>>(Wp2, Wfin);
    yc_kernel<<<dim3(Tn / 32, Bn), 160>>>(y, Wpc);
    z_kernel<<<dim3(Tn / 32, Bn), 256>>>(y);
    main_kernel<<<dim3(Tn, Bn), 128>>>(WBASE, WBIAS, Wpre, patches, pproj, out);
}

// round 4
// speedup vs baseline: 1.5824x; 1.5824x over previous
#include <cuda_runtime.h>
#include <cuda_bf16.h>
#include <cstdint>

#define Tn   4096
#define Cn   512
#define Pn   64
#define PSn  16
#define CSn  5
#define MBn  128
#define FDn  128
#define Bn   2
#define TT   32          // t-tile of main kernel
#define ZBT  64          // t-tile of z kernel
#define ZBK  32          // k-tile of z kernel

// Scratch (device globals; no allocation allowed)
__device__ __align__(16) float g_wcomb[Cn * FDn];          // W_proj2 @ W_FINAL
__device__ __align__(16) float g_z[Bn * Tn * FDn];         // y @ Wcomb (4 MB)
__device__ __align__(16) float g_yc[Bn * Tn * CSn];        // y @ W_proj_comp, stride 5

__device__ __forceinline__ unsigned long long ffma2(unsigned long long a,
                                                    unsigned long long b,
                                                    unsigned long long c) {
    unsigned long long d;
    asm("fma.rn.f32x2 %0, %1, %2, %3;" : "=l"(d) : "l"(a), "l"(b), "l"(c));
    return d;
}
__device__ __forceinline__ unsigned long long dup2(float v) {
    unsigned int u = __float_as_uint(v);
    return ((unsigned long long)u << 32) | (unsigned long long)u;
}

// ---------------------------------------------------------------------------
// Wcomb[c][f] = sum_m W_proj2[c][m] * W_FINAL[m][f]
// ---------------------------------------------------------------------------
__global__ void wcomb_kernel(const float* __restrict__ Wp2,
                             const float* __restrict__ Wfin) {
    __shared__ float wp[4][MBn];
    const int tid = threadIdx.x;
    const int c0 = blockIdx.x * 4;
#pragma unroll
    for (int i = 0; i < 4; i++)
        wp[i][tid] = Wp2[(c0 + i) * MBn + tid];
    __syncthreads();
    float a0 = 0.f, a1 = 0.f, a2 = 0.f, a3 = 0.f;
#pragma unroll 8
    for (int m = 0; m < MBn; m++) {
        const float wf = Wfin[m * FDn + tid];
        a0 += wp[0][m] * wf; a1 += wp[1][m] * wf;
        a2 += wp[2][m] * wf; a3 += wp[3][m] * wf;
    }
    g_wcomb[(c0 + 0) * FDn + tid] = a0;
    g_wcomb[(c0 + 1) * FDn + tid] = a1;
    g_wcomb[(c0 + 2) * FDn + tid] = a2;
    g_wcomb[(c0 + 3) * FDn + tid] = a3;
}

// ---------------------------------------------------------------------------
// yc[b][t][k] = sum_c y[b][t][c] * W_proj_comp[c][k]  (stride-5 compact rows)
// 4 lanes per t-row, shfl reduce. grid (T/64, B), 256 threads.
// ---------------------------------------------------------------------------
__global__ void __launch_bounds__(256) yc_kernel(const float* __restrict__ y,
                                                 const float* __restrict__ Wpc) {
    const int b  = blockIdx.y;
    const int tl = threadIdx.x >> 2;
    const int q  = threadIdx.x & 3;
    const int t  = blockIdx.x * 64 + tl;
    const float* yr = y + ((size_t)b * Tn + t) * Cn + q * 128;
    float a0 = 0.f, a1 = 0.f, a2 = 0.f, a3 = 0.f, a4 = 0.f;
#pragma unroll 4
    for (int c4 = 0; c4 < 32; c4++) {
        const float4 v = *(const float4*)(yr + c4 * 4);
        const float* w = Wpc + (q * 128 + c4 * 4) * CSn;
        a0 += v.x * __ldg(w + 0) + v.y * __ldg(w + 5) + v.z * __ldg(w + 10) + v.w * __ldg(w + 15);
        a1 += v.x * __ldg(w + 1) + v.y * __ldg(w + 6) + v.z * __ldg(w + 11) + v.w * __ldg(w + 16);
        a2 += v.x * __ldg(w + 2) + v.y * __ldg(w + 7) + v.z * __ldg(w + 12) + v.w * __ldg(w + 17);
        a3 += v.x * __ldg(w + 3) + v.y * __ldg(w + 8) + v.z * __ldg(w + 13) + v.w * __ldg(w + 18);
        a4 += v.x * __ldg(w + 4) + v.y * __ldg(w + 9) + v.z * __ldg(w + 14) + v.w * __ldg(w + 19);
    }
#pragma unroll
    for (int off = 1; off < 4; off <<= 1) {
        a0 += __shfl_xor_sync(0xFFFFFFFF, a0, off);
        a1 += __shfl_xor_sync(0xFFFFFFFF, a1, off);
        a2 += __shfl_xor_sync(0xFFFFFFFF, a2, off);
        a3 += __shfl_xor_sync(0xFFFFFFFF, a3, off);
        a4 += __shfl_xor_sync(0xFFFFFFFF, a4, off);
    }
    if (q == 0) {
        float* o = g_yc + ((size_t)b * Tn + t) * CSn;
        o[0] = a0; o[1] = a1; o[2] = a2; o[3] = a3; o[4] = a4;
    }
}

// ---------------------------------------------------------------------------
// z = y @ Wcomb via fma.rn.f32x2. Block = 64t x 128m, 256 threads, grid 128.
// Lane layout 8(t-groups) x 4(m-groups); thread tile 8t x 4m.
// y staged pre-duplicated (f32x2 both halves), w read as conflict-free LDS.128.
// ---------------------------------------------------------------------------
__global__ void __launch_bounds__(256) z_kernel(const float* __restrict__ y) {
    __shared__ __align__(16) float ws[ZBK * 128];
    __shared__ unsigned long long ysD[ZBK * ZBT];
    const int b    = blockIdx.y;
    const int t0   = blockIdx.x * ZBT;
    const int tid  = threadIdx.x;
    const int warp = tid >> 5;
    const int lane = tid & 31;
    const int tg   = lane & 7;
    const int mg   = lane >> 3;
    const int moff = warp * 16 + mg * 4;

    unsigned long long acc[8][2];
#pragma unroll
    for (int i = 0; i < 8; i++) { acc[i][0] = 0ull; acc[i][1] = 0ull; }

    const int st  = tid >> 2;            // staging t 0..63
    const int skg = (tid & 3) * 8;       // staging k base
    const float* ybase = y + ((size_t)b * Tn + t0 + st) * Cn;

    for (int c0 = 0; c0 < Cn; c0 += ZBK) {
        // stage W tile (coalesced)
        const float4* src4 = (const float4*)(g_wcomb + c0 * 128);
#pragma unroll
        for (int i = 0; i < 4; i++)
            ((float4*)ws)[tid + i * 256] = src4[tid + i * 256];
        // stage y tile dup-packed: [k][t]
        {
            const float4 v0 = *(const float4*)(ybase + c0 + skg);
            const float4 v1 = *(const float4*)(ybase + c0 + skg + 4);
            ysD[(skg + 0) * ZBT + st] = dup2(v0.x);
            ysD[(skg + 1) * ZBT + st] = dup2(v0.y);
            ysD[(skg + 2) * ZBT + st] = dup2(v0.z);
            ysD[(skg + 3) * ZBT + st] = dup2(v0.w);
            ysD[(skg + 4) * ZBT + st] = dup2(v1.x);
            ysD[(skg + 5) * ZBT + st] = dup2(v1.y);
            ysD[(skg + 6) * ZBT + st] = dup2(v1.z);
            ysD[(skg + 7) * ZBT + st] = dup2(v1.w);
        }
        __syncthreads();
#pragma unroll 8
        for (int k = 0; k < ZBK; k++) {
            const ulonglong2 wv = *(const ulonglong2*)(ws + k * 128 + moff);
#pragma unroll
            for (int i = 0; i < 8; i++) {
                const unsigned long long yv = ysD[k * ZBT + tg + 8 * i];
                acc[i][0] = ffma2(yv, wv.x, acc[i][0]);
                acc[i][1] = ffma2(yv, wv.y, acc[i][1]);
            }
        }
        __syncthreads();
    }
#pragma unroll
    for (int i = 0; i < 8; i++) {
        ulonglong2 o; o.x = acc[i][0]; o.y = acc[i][1];
        *(ulonglong2*)(g_z + ((size_t)b * Tn + t0 + tg + 8 * i) * FDn + moff) = o;
    }
}

// ---------------------------------------------------------------------------
// Main fused kernel: 32 t per block, 256 threads, yc table resident in SMEM.
// smem words: syc 20480 | sWB 64*81 | sWpre 4096 | sres 2048 | smix 2048
//             | spp 2048 (int) | spat 8192 (int)  => 176384 bytes
// ---------------------------------------------------------------------------
#define MAIN_SMEM_BYTES ((Tn*CSn + Pn*81 + Pn*Pn + TT*Pn + TT*Pn)*4 + (TT*Pn + 8*Pn*PSn)*4)

__global__ void __launch_bounds__(256)
main_kernel(const float* __restrict__ WBASE,
            const float* __restrict__ WBIAS,
            const float* __restrict__ Wpre,
            const int*   __restrict__ patches,
            const int*   __restrict__ pproj,
            float*       __restrict__ out) {
    extern __shared__ __align__(16) char sm_raw[];
    float* syc   = (float*)sm_raw;            // [4096][5]
    float* sWB   = syc + Tn * CSn;            // [64][81] (padded 80->81)
    float* sWpre = sWB + Pn * 81;             // [64][64]
    float* sres  = sWpre + Pn * Pn;           // [32][64]
    float* smix  = sres + TT * Pn;            // [32][64]
    int*   spp   = (int*)(smix + TT * Pn);    // [32][64]
    int*   spat  = spp + TT * Pn;             // [8][16][64] (transposed chunk)

    const int b   = blockIdx.y;
    const int t0  = blockIdx.x * TT;
    const int tid = threadIdx.x;

    // ---- stage tables ----
    {
        const float4* src = (const float4*)(g_yc + (size_t)b * Tn * CSn);
        float4* dst = (float4*)syc;
#pragma unroll
        for (int i = tid; i < (Tn * CSn) / 4; i += 256) dst[i] = src[i];
    }
    for (int i = tid; i < Pn * PSn * CSn; i += 256)
        sWB[(i / 80) * 81 + (i % 80)] = WBASE[i];
    {
        const float4* src = (const float4*)Wpre;
        float4* dst = (float4*)sWpre;
        for (int i = tid; i < (Pn * Pn) / 4; i += 256) dst[i] = src[i];
    }
    {
        const int4* src = (const int4*)(pproj + (size_t)t0 * Pn);
        int4* dst = (int4*)spp;
        for (int i = tid; i < (TT * Pn) / 4; i += 256) dst[i] = src[i];
    }
    __syncthreads();

    // ---- res phase over 4 chunks of 8 t ----
    const int p  = tid & 63;
    const int tq = tid >> 6;
    const float bias = __ldg(WBIAS + p);
    for (int c4 = 0; c4 < 4; c4++) {
        // stage patches chunk transposed to [tl][s][p]
        const int4* src = (const int4*)(patches + (size_t)(t0 + c4 * 8) * (Pn * PSn));
        for (int i = tid; i < (8 * Pn * PSn) / 4; i += 256) {
            const int4 v  = src[i];
            const int gi  = i * 4;
            const int tl  = gi >> 10;
            const int rem = gi & 1023;
            const int pp  = rem >> 4;
            const int s0  = rem & 15;
            int* dst = spat + tl * 1024 + pp;
            dst[(s0 + 0) * 64] = v.x;
            dst[(s0 + 1) * 64] = v.y;
            dst[(s0 + 2) * 64] = v.z;
            dst[(s0 + 3) * 64] = v.w;
        }
        __syncthreads();
        const float* wb = sWB + p * 81;
#pragma unroll
        for (int r = 0; r < 2; r++) {
            const int tl = tq + 4 * r;
            const int* sp = spat + tl * 1024 + p;
            float acc = 0.f;
#pragma unroll
            for (int s = 0; s < PSn; s++) {
                const int idx = sp[s * 64];
                const float* yr = syc + idx * CSn;
                const float* w  = wb + s * CSn;
                acc += yr[0] * w[0] + yr[1] * w[1] + yr[2] * w[2]
                     + yr[3] * w[3] + yr[4] * w[4];
            }
            sres[(c4 * 8 + tl) * Pn + p] = acc + bias;
        }
        __syncthreads();
    }

    // ---- mix: q = tid&63, tg handles t in {tg + 4j} ----
    {
        const int q   = tid & 63;
        const int tg2 = tid >> 6;
        float acc[8];
#pragma unroll
        for (int j = 0; j < 8; j++) acc[j] = 0.f;
#pragma unroll 8
        for (int pp = 0; pp < Pn; pp++) {
            const float w = sWpre[pp * Pn + q];
#pragma unroll
            for (int j = 0; j < 8; j++)
                acc[j] += sres[(tg2 + 4 * j) * Pn + pp] * w;
        }
#pragma unroll
        for (int j = 0; j < 8; j++)
            smix[(tg2 + 4 * j) * Pn + q] = acc[j];
    }
    __syncthreads();

    // ---- final: coalesced z-row gathers ----
    {
        const int f  = tid & 127;
        const int th = tid >> 7;
        const float* zb = g_z + (size_t)b * Tn * FDn + f;
        for (int tt = th; tt < TT; tt += 2) {
            const float* mx = smix + tt * Pn;
            const int*   pr = spp + tt * Pn;
            float o0 = 0.f, o1 = 0.f, o2 = 0.f, o3 = 0.f;
#pragma unroll
            for (int p4 = 0; p4 < Pn; p4 += 4) {
                o0 += mx[p4 + 0] * __ldg(zb + (size_t)pr[p4 + 0] * FDn);
                o1 += mx[p4 + 1] * __ldg(zb + (size_t)pr[p4 + 1] * FDn);
                o2 += mx[p4 + 2] * __ldg(zb + (size_t)pr[p4 + 2] * FDn);
                o3 += mx[p4 + 3] * __ldg(zb + (size_t)pr[p4 + 3] * FDn);
            }
            out[((size_t)b * Tn + t0 + tt) * FDn + f] = (o0 + o1) + (o2 + o3);
        }
    }
}

// ---------------------------------------------------------------------------
extern "C" void kernel_launch(void* const* d_in, const int* in_sizes, int n_in,
                              void* d_out, int out_size) {
    const float* y     = (const float*)d_in[0];
    const float* WBASE = (const float*)d_in[1];
    const float* WBIAS = (const float*)d_in[2];
    const float* Wp2   = (const float*)d_in[3];
    const float* Wpc   = (const float*)d_in[4];
    const float* Wpre  = (const float*)d_in[5];
    const float* Wfin  = (const float*)d_in[6];
    const int*   patches = (const int*)d_in[7];
    const int*   pproj   = (const int*)d_in[8];
    float* out = (float*)d_out;

    cudaFuncSetAttribute(main_kernel,
                         cudaFuncAttributeMaxDynamicSharedMemorySize,
                         MAIN_SMEM_BYTES);

    wcomb_kernel<<<128, 128>>>(Wp2, Wfin);
    yc_kernel<<<dim3(Tn / 64, Bn), 256>>>(y, Wpc);
    z_kernel<<<dim3(Tn / ZBT, Bn), 256>>>(y);
    main_kernel<<<dim3(Tn / TT, Bn), 256, MAIN_SMEM_BYTES>>>(
        WBASE, WBIAS, Wpre, patches, pproj, out);
}

// round 5
// speedup vs baseline: 1.7696x; 1.1183x over previous
#include <cuda_runtime.h>
#include <cuda_bf16.h>
#include <cstdint>

#define Tn   4096
#define Cn   512
#define Pn   64
#define PSn  16
#define CSn  5
#define MBn  128
#define FDn  128
#define Bn   2
#define TT   32          // t-tile of res/mix kernel
#define FT   16          // t-tile of final kernel
#define ZBT  64          // t-tile of z kernel
#define ZBK  32          // k-tile of z kernel

// Scratch (device globals; no allocation allowed)
__device__ __align__(16) float g_wcomb[Cn * FDn];          // W_proj2 @ W_FINAL
__device__ __align__(16) float g_z[Bn * Tn * FDn];         // y @ Wcomb (4 MB)
__device__ __align__(16) float g_yc[Bn * Tn * CSn];        // y @ W_proj_comp
__device__ __align__(16) float g_mix[Bn * Tn * Pn];        // res @ W_presoftmax1 (2 MB)

__device__ __forceinline__ unsigned long long ffma2(unsigned long long a,
                                                    unsigned long long b,
                                                    unsigned long long c) {
    unsigned long long d;
    asm("fma.rn.f32x2 %0, %1, %2, %3;" : "=l"(d) : "l"(a), "l"(b), "l"(c));
    return d;
}
__device__ __forceinline__ unsigned long long dup2(float v) {
    unsigned int u = __float_as_uint(v);
    return ((unsigned long long)u << 32) | (unsigned long long)u;
}

// ---------------------------------------------------------------------------
// Wcomb[c][f] = sum_m W_proj2[c][m] * W_FINAL[m][f]
// ---------------------------------------------------------------------------
__global__ void wcomb_kernel(const float* __restrict__ Wp2,
                             const float* __restrict__ Wfin) {
    __shared__ float wp[4][MBn];
    const int tid = threadIdx.x;
    const int c0 = blockIdx.x * 4;
#pragma unroll
    for (int i = 0; i < 4; i++)
        wp[i][tid] = Wp2[(c0 + i) * MBn + tid];
    __syncthreads();
    float a0 = 0.f, a1 = 0.f, a2 = 0.f, a3 = 0.f;
#pragma unroll 8
    for (int m = 0; m < MBn; m++) {
        const float wf = Wfin[m * FDn + tid];
        a0 += wp[0][m] * wf; a1 += wp[1][m] * wf;
        a2 += wp[2][m] * wf; a3 += wp[3][m] * wf;
    }
    g_wcomb[(c0 + 0) * FDn + tid] = a0;
    g_wcomb[(c0 + 1) * FDn + tid] = a1;
    g_wcomb[(c0 + 2) * FDn + tid] = a2;
    g_wcomb[(c0 + 3) * FDn + tid] = a3;
}

// ---------------------------------------------------------------------------
// yc[b][t][k] = sum_c y[b][t][c] * W_proj_comp[c][k]  (stride-5 compact rows)
// ---------------------------------------------------------------------------
__global__ void __launch_bounds__(256) yc_kernel(const float* __restrict__ y,
                                                 const float* __restrict__ Wpc) {
    const int b  = blockIdx.y;
    const int tl = threadIdx.x >> 2;
    const int q  = threadIdx.x & 3;
    const int t  = blockIdx.x * 64 + tl;
    const float* yr = y + ((size_t)b * Tn + t) * Cn + q * 128;
    float a0 = 0.f, a1 = 0.f, a2 = 0.f, a3 = 0.f, a4 = 0.f;
#pragma unroll 4
    for (int c4 = 0; c4 < 32; c4++) {
        const float4 v = *(const float4*)(yr + c4 * 4);
        const float* w = Wpc + (q * 128 + c4 * 4) * CSn;
        a0 += v.x * __ldg(w + 0) + v.y * __ldg(w + 5) + v.z * __ldg(w + 10) + v.w * __ldg(w + 15);
        a1 += v.x * __ldg(w + 1) + v.y * __ldg(w + 6) + v.z * __ldg(w + 11) + v.w * __ldg(w + 16);
        a2 += v.x * __ldg(w + 2) + v.y * __ldg(w + 7) + v.z * __ldg(w + 12) + v.w * __ldg(w + 17);
        a3 += v.x * __ldg(w + 3) + v.y * __ldg(w + 8) + v.z * __ldg(w + 13) + v.w * __ldg(w + 18);
        a4 += v.x * __ldg(w + 4) + v.y * __ldg(w + 9) + v.z * __ldg(w + 14) + v.w * __ldg(w + 19);
    }
#pragma unroll
    for (int off = 1; off < 4; off <<= 1) {
        a0 += __shfl_xor_sync(0xFFFFFFFF, a0, off);
        a1 += __shfl_xor_sync(0xFFFFFFFF, a1, off);
        a2 += __shfl_xor_sync(0xFFFFFFFF, a2, off);
        a3 += __shfl_xor_sync(0xFFFFFFFF, a3, off);
        a4 += __shfl_xor_sync(0xFFFFFFFF, a4, off);
    }
    if (q == 0) {
        float* o = g_yc + ((size_t)b * Tn + t) * CSn;
        o[0] = a0; o[1] = a1; o[2] = a2; o[3] = a3; o[4] = a4;
    }
}

// ---------------------------------------------------------------------------
// z = y @ Wcomb via fma.rn.f32x2. Block = 64t x 128m, 256 threads, grid 128.
// ---------------------------------------------------------------------------
__global__ void __launch_bounds__(256) z_kernel(const float* __restrict__ y) {
    __shared__ __align__(16) float ws[ZBK * 128];
    __shared__ unsigned long long ysD[ZBK * ZBT];
    const int b    = blockIdx.y;
    const int t0   = blockIdx.x * ZBT;
    const int tid  = threadIdx.x;
    const int warp = tid >> 5;
    const int lane = tid & 31;
    const int tg   = lane & 7;
    const int mg   = lane >> 3;
    const int moff = warp * 16 + mg * 4;

    unsigned long long acc[8][2];
#pragma unroll
    for (int i = 0; i < 8; i++) { acc[i][0] = 0ull; acc[i][1] = 0ull; }

    const int st  = tid >> 2;
    const int skg = (tid & 3) * 8;
    const float* ybase = y + ((size_t)b * Tn + t0 + st) * Cn;

    for (int c0 = 0; c0 < Cn; c0 += ZBK) {
        const float4* src4 = (const float4*)(g_wcomb + c0 * 128);
#pragma unroll
        for (int i = 0; i < 4; i++)
            ((float4*)ws)[tid + i * 256] = src4[tid + i * 256];
        {
            const float4 v0 = *(const float4*)(ybase + c0 + skg);
            const float4 v1 = *(const float4*)(ybase + c0 + skg + 4);
            ysD[(skg + 0) * ZBT + st] = dup2(v0.x);
            ysD[(skg + 1) * ZBT + st] = dup2(v0.y);
            ysD[(skg + 2) * ZBT + st] = dup2(v0.z);
            ysD[(skg + 3) * ZBT + st] = dup2(v0.w);
            ysD[(skg + 4) * ZBT + st] = dup2(v1.x);
            ysD[(skg + 5) * ZBT + st] = dup2(v1.y);
            ysD[(skg + 6) * ZBT + st] = dup2(v1.z);
            ysD[(skg + 7) * ZBT + st] = dup2(v1.w);
        }
        __syncthreads();
#pragma unroll 8
        for (int k = 0; k < ZBK; k++) {
            const ulonglong2 wv = *(const ulonglong2*)(ws + k * 128 + moff);
#pragma unroll
            for (int i = 0; i < 8; i++) {
                const unsigned long long yv = ysD[k * ZBT + tg + 8 * i];
                acc[i][0] = ffma2(yv, wv.x, acc[i][0]);
                acc[i][1] = ffma2(yv, wv.y, acc[i][1]);
            }
        }
        __syncthreads();
    }
#pragma unroll
    for (int i = 0; i < 8; i++) {
        ulonglong2 o; o.x = acc[i][0]; o.y = acc[i][1];
        *(ulonglong2*)(g_z + ((size_t)b * Tn + t0 + tg + 8 * i) * FDn + moff) = o;
    }
}

// ---------------------------------------------------------------------------
// M1: res + mix, 512 threads, TT=32 t per block, yc table in SMEM.
// smem: syc 80KB | sWB 64*81 | sWpre 4096 | sres 2048 | spat 8192(int)
// ---------------------------------------------------------------------------
#define M1_SMEM_BYTES ((Tn*CSn + Pn*81 + Pn*Pn + TT*Pn)*4 + (8*Pn*PSn)*4)

__global__ void __launch_bounds__(512)
resmix_kernel(const float* __restrict__ WBASE,
              const float* __restrict__ WBIAS,
              const float* __restrict__ Wpre,
              const int*   __restrict__ patches) {
    extern __shared__ __align__(16) char sm_raw[];
    float* syc   = (float*)sm_raw;            // [4096][5]
    float* sWB   = syc + Tn * CSn;            // [64][81]
    float* sWpre = sWB + Pn * 81;             // [64][64]
    float* sres  = sWpre + Pn * Pn;           // [32][64]
    int*   spat  = (int*)(sres + TT * Pn);    // [8][16][64]

    const int b   = blockIdx.y;
    const int t0  = blockIdx.x * TT;
    const int tid = threadIdx.x;

    // ---- stage tables ----
    {
        const float4* src = (const float4*)(g_yc + (size_t)b * Tn * CSn);
        float4* dst = (float4*)syc;
#pragma unroll
        for (int i = tid; i < (Tn * CSn) / 4; i += 512) dst[i] = src[i];
    }
    for (int i = tid; i < Pn * PSn * CSn; i += 512)
        sWB[(i / 80) * 81 + (i % 80)] = WBASE[i];
    {
        const float4* src = (const float4*)Wpre;
        float4* dst = (float4*)sWpre;
        for (int i = tid; i < (Pn * Pn) / 4; i += 512) dst[i] = src[i];
    }
    __syncthreads();

    // ---- res over 4 chunks of 8 t; thread = (p = tid&63, tl = tid>>6) ----
    const int p  = tid & 63;
    const int tl = tid >> 6;
    const float bias = __ldg(WBIAS + p);
    const float* wb = sWB + p * 81;
    for (int c4 = 0; c4 < 4; c4++) {
        // stage patches chunk transposed to [tl][s][p]
        const int4* src = (const int4*)(patches + (size_t)(t0 + c4 * 8) * (Pn * PSn));
#pragma unroll
        for (int i = tid; i < (8 * Pn * PSn) / 4; i += 512) {
            const int4 v  = src[i];
            const int gi  = i * 4;
            const int tt  = gi >> 10;
            const int rem = gi & 1023;
            const int pp  = rem >> 4;
            const int s0  = rem & 15;
            int* dst = spat + tt * 1024 + pp;
            dst[(s0 + 0) * 64] = v.x;
            dst[(s0 + 1) * 64] = v.y;
            dst[(s0 + 2) * 64] = v.z;
            dst[(s0 + 3) * 64] = v.w;
        }
        __syncthreads();
        {
            const int* sp = spat + tl * 1024 + p;
            float acc = 0.f;
#pragma unroll
            for (int s = 0; s < PSn; s++) {
                const int idx = sp[s * 64];
                const float* yr = syc + idx * CSn;
                const float* w  = wb + s * CSn;
                acc += yr[0] * w[0] + yr[1] * w[1] + yr[2] * w[2]
                     + yr[3] * w[3] + yr[4] * w[4];
            }
            sres[(c4 * 8 + tl) * Pn + p] = acc + bias;
        }
        __syncthreads();
    }

    // ---- mix: q = tid&63, tg handles t in {tg + 8j} ----
    {
        const int q  = tid & 63;
        const int tg = tid >> 6;
        float acc[4];
#pragma unroll
        for (int j = 0; j < 4; j++) acc[j] = 0.f;
#pragma unroll 8
        for (int pp = 0; pp < Pn; pp++) {
            const float w = sWpre[pp * Pn + q];
#pragma unroll
            for (int j = 0; j < 4; j++)
                acc[j] += sres[(tg + 8 * j) * Pn + pp] * w;
        }
#pragma unroll
        for (int j = 0; j < 4; j++)
            g_mix[((size_t)b * Tn + t0 + tg + 8 * j) * Pn + q] = acc[j];
    }
}

// ---------------------------------------------------------------------------
// M2: out[b,t,f] = sum_p mix[b,t,p] * z[b, pproj[t,p], f]
// 16 t per block, 256 threads = 32 lanes(f4) x 8 t-rows. High occupancy,
// one LDG.128 per warp covers a full 512B z-row.
// ---------------------------------------------------------------------------
__global__ void __launch_bounds__(256)
final_kernel(const int* __restrict__ pproj, float* __restrict__ out) {
    __shared__ float smix[FT * Pn];
    __shared__ int   spp[FT * Pn];
    const int b   = blockIdx.y;
    const int t0  = blockIdx.x * FT;
    const int tid = threadIdx.x;

    {
        const float4* ms = (const float4*)(g_mix + ((size_t)b * Tn + t0) * Pn);
        ((float4*)smix)[tid] = ms[tid];
        const int4* ps = (const int4*)(pproj + (size_t)t0 * Pn);
        ((int4*)spp)[tid] = ps[tid];
    }
    __syncthreads();

    const int lane = tid & 31;
    const int th   = tid >> 5;                 // 8 t-row groups
    const float4* zb = (const float4*)(g_z + (size_t)b * Tn * FDn) + lane;
#pragma unroll
    for (int j = 0; j < 2; j++) {
        const int tt = th * 2 + j;
        const float* mx = smix + tt * Pn;
        const int*   pr = spp + tt * Pn;
        float4 a0 = {0,0,0,0}, a1 = {0,0,0,0}, a2 = {0,0,0,0}, a3 = {0,0,0,0};
#pragma unroll
        for (int p4 = 0; p4 < Pn; p4 += 4) {
            const float4 v0 = __ldg(zb + (size_t)pr[p4 + 0] * 32);
            const float4 v1 = __ldg(zb + (size_t)pr[p4 + 1] * 32);
            const float4 v2 = __ldg(zb + (size_t)pr[p4 + 2] * 32);
            const float4 v3 = __ldg(zb + (size_t)pr[p4 + 3] * 32);
            const float m0 = mx[p4 + 0], m1 = mx[p4 + 1];
            const float m2 = mx[p4 + 2], m3 = mx[p4 + 3];
            a0.x += m0 * v0.x; a0.y += m0 * v0.y; a0.z += m0 * v0.z; a0.w += m0 * v0.w;
            a1.x += m1 * v1.x; a1.y += m1 * v1.y; a1.z += m1 * v1.z; a1.w += m1 * v1.w;
            a2.x += m2 * v2.x; a2.y += m2 * v2.y; a2.z += m2 * v2.z; a2.w += m2 * v2.w;
            a3.x += m3 * v3.x; a3.y += m3 * v3.y; a3.z += m3 * v3.z; a3.w += m3 * v3.w;
        }
        float4 o;
        o.x = (a0.x + a1.x) + (a2.x + a3.x);
        o.y = (a0.y + a1.y) + (a2.y + a3.y);
        o.z = (a0.z + a1.z) + (a2.z + a3.z);
        o.w = (a0.w + a1.w) + (a2.w + a3.w);
        ((float4*)(out + ((size_t)b * Tn + t0 + tt) * FDn))[lane] = o;
    }
}

// ---------------------------------------------------------------------------
extern "C" void kernel_launch(void* const* d_in, const int* in_sizes, int n_in,
                              void* d_out, int out_size) {
    const float* y     = (const float*)d_in[0];
    const float* WBASE = (const float*)d_in[1];
    const float* WBIAS = (const float*)d_in[2];
    const float* Wp2   = (const float*)d_in[3];
    const float* Wpc   = (const float*)d_in[4];
    const float* Wpre  = (const float*)d_in[5];
    const float* Wfin  = (const float*)d_in[6];
    const int*   patches = (const int*)d_in[7];
    const int*   pproj   = (const int*)d_in[8];
    float* out = (float*)d_out;

    cudaFuncSetAttribute(resmix_kernel,
                         cudaFuncAttributeMaxDynamicSharedMemorySize,
                         M1_SMEM_BYTES);

    wcomb_kernel<<<128, 128>>>(Wp2, Wfin);
    yc_kernel<<<dim3(Tn / 64, Bn), 256>>>(y, Wpc);
    z_kernel<<<dim3(Tn / ZBT, Bn), 256>>>(y);
    resmix_kernel<<<dim3(Tn / TT, Bn), 512, M1_SMEM_BYTES>>>(
        WBASE, WBIAS, Wpre, patches);
    final_kernel<<<dim3(Tn / FT, Bn), 256>>>(pproj, out);
}

// round 6
// speedup vs baseline: 1.8489x; 1.0448x over previous
#include <cuda_runtime.h>
#include <cuda_bf16.h>
#include <cstdint>

#define Tn   4096
#define Cn   512
#define Pn   64
#define PSn  16
#define CSn  5
#define MBn  128
#define FDn  128
#define Bn   2
#define TT   64          // t-tile of res/mix kernel
#define FT   16          // t-tile of final kernel
#define ZBT  64          // t-tile of z kernel
#define ZBK  32          // k-tile of z kernel

// Scratch (device globals; no allocation allowed)
__device__ __align__(16) float g_wcomb[Cn * FDn];          // W_proj2 @ W_FINAL
__device__ __align__(16) float g_z[Bn * Tn * FDn];         // y @ Wcomb (4 MB)
__device__ __align__(16) float g_yc[Bn * Tn * CSn];        // y @ W_proj_comp
__device__ __align__(16) float g_mix[Bn * Tn * Pn];        // res @ W_presoftmax1 (2 MB)

__device__ __forceinline__ unsigned long long ffma2(unsigned long long a,
                                                    unsigned long long b,
                                                    unsigned long long c) {
    unsigned long long d;
    asm("fma.rn.f32x2 %0, %1, %2, %3;" : "=l"(d) : "l"(a), "l"(b), "l"(c));
    return d;
}
__device__ __forceinline__ unsigned long long dup2(float v) {
    unsigned int u = __float_as_uint(v);
    return ((unsigned long long)u << 32) | (unsigned long long)u;
}

// ---------------------------------------------------------------------------
// Wcomb[c][f] = sum_m W_proj2[c][m] * W_FINAL[m][f]
// ---------------------------------------------------------------------------
__global__ void wcomb_kernel(const float* __restrict__ Wp2,
                             const float* __restrict__ Wfin) {
    __shared__ float wp[4][MBn];
    const int tid = threadIdx.x;
    const int c0 = blockIdx.x * 4;
#pragma unroll
    for (int i = 0; i < 4; i++)
        wp[i][tid] = Wp2[(c0 + i) * MBn + tid];
    __syncthreads();
    float a0 = 0.f, a1 = 0.f, a2 = 0.f, a3 = 0.f;
#pragma unroll 8
    for (int m = 0; m < MBn; m++) {
        const float wf = Wfin[m * FDn + tid];
        a0 += wp[0][m] * wf; a1 += wp[1][m] * wf;
        a2 += wp[2][m] * wf; a3 += wp[3][m] * wf;
    }
    g_wcomb[(c0 + 0) * FDn + tid] = a0;
    g_wcomb[(c0 + 1) * FDn + tid] = a1;
    g_wcomb[(c0 + 2) * FDn + tid] = a2;
    g_wcomb[(c0 + 3) * FDn + tid] = a3;
}

// ---------------------------------------------------------------------------
// yc[b][t][k] = sum_c y[b][t][c] * W_proj_comp[c][k]  (stride-5 compact rows)
// ---------------------------------------------------------------------------
__global__ void __launch_bounds__(256) yc_kernel(const float* __restrict__ y,
                                                 const float* __restrict__ Wpc) {
    const int b  = blockIdx.y;
    const int tl = threadIdx.x >> 2;
    const int q  = threadIdx.x & 3;
    const int t  = blockIdx.x * 64 + tl;
    const float* yr = y + ((size_t)b * Tn + t) * Cn + q * 128;
    float a0 = 0.f, a1 = 0.f, a2 = 0.f, a3 = 0.f, a4 = 0.f;
#pragma unroll 4
    for (int c4 = 0; c4 < 32; c4++) {
        const float4 v = *(const float4*)(yr + c4 * 4);
        const float* w = Wpc + (q * 128 + c4 * 4) * CSn;
        a0 += v.x * __ldg(w + 0) + v.y * __ldg(w + 5) + v.z * __ldg(w + 10) + v.w * __ldg(w + 15);
        a1 += v.x * __ldg(w + 1) + v.y * __ldg(w + 6) + v.z * __ldg(w + 11) + v.w * __ldg(w + 16);
        a2 += v.x * __ldg(w + 2) + v.y * __ldg(w + 7) + v.z * __ldg(w + 12) + v.w * __ldg(w + 17);
        a3 += v.x * __ldg(w + 3) + v.y * __ldg(w + 8) + v.z * __ldg(w + 13) + v.w * __ldg(w + 18);
        a4 += v.x * __ldg(w + 4) + v.y * __ldg(w + 9) + v.z * __ldg(w + 14) + v.w * __ldg(w + 19);
    }
#pragma unroll
    for (int off = 1; off < 4; off <<= 1) {
        a0 += __shfl_xor_sync(0xFFFFFFFF, a0, off);
        a1 += __shfl_xor_sync(0xFFFFFFFF, a1, off);
        a2 += __shfl_xor_sync(0xFFFFFFFF, a2, off);
        a3 += __shfl_xor_sync(0xFFFFFFFF, a3, off);
        a4 += __shfl_xor_sync(0xFFFFFFFF, a4, off);
    }
    if (q == 0) {
        float* o = g_yc + ((size_t)b * Tn + t) * CSn;
        o[0] = a0; o[1] = a1; o[2] = a2; o[3] = a3; o[4] = a4;
    }
}

// ---------------------------------------------------------------------------
// z = y @ Wcomb via fma.rn.f32x2. Block = 64t x 128m, 256 threads, grid 128.
// ---------------------------------------------------------------------------
__global__ void __launch_bounds__(256) z_kernel(const float* __restrict__ y) {
    __shared__ __align__(16) float ws[ZBK * 128];
    __shared__ unsigned long long ysD[ZBK * ZBT];
    const int b    = blockIdx.y;
    const int t0   = blockIdx.x * ZBT;
    const int tid  = threadIdx.x;
    const int warp = tid >> 5;
    const int lane = tid & 31;
    const int tg   = lane & 7;
    const int mg   = lane >> 3;
    const int moff = warp * 16 + mg * 4;

    unsigned long long acc[8][2];
#pragma unroll
    for (int i = 0; i < 8; i++) { acc[i][0] = 0ull; acc[i][1] = 0ull; }

    const int st  = tid >> 2;
    const int skg = (tid & 3) * 8;
    const float* ybase = y + ((size_t)b * Tn + t0 + st) * Cn;

    for (int c0 = 0; c0 < Cn; c0 += ZBK) {
        const float4* src4 = (const float4*)(g_wcomb + c0 * 128);
#pragma unroll
        for (int i = 0; i < 4; i++)
            ((float4*)ws)[tid + i * 256] = src4[tid + i * 256];
        {
            const float4 v0 = *(const float4*)(ybase + c0 + skg);
            const float4 v1 = *(const float4*)(ybase + c0 + skg + 4);
            ysD[(skg + 0) * ZBT + st] = dup2(v0.x);
            ysD[(skg + 1) * ZBT + st] = dup2(v0.y);
            ysD[(skg + 2) * ZBT + st] = dup2(v0.z);
            ysD[(skg + 3) * ZBT + st] = dup2(v0.w);
            ysD[(skg + 4) * ZBT + st] = dup2(v1.x);
            ysD[(skg + 5) * ZBT + st] = dup2(v1.y);
            ysD[(skg + 6) * ZBT + st] = dup2(v1.z);
            ysD[(skg + 7) * ZBT + st] = dup2(v1.w);
        }
        __syncthreads();
#pragma unroll 8
        for (int k = 0; k < ZBK; k++) {
            const ulonglong2 wv = *(const ulonglong2*)(ws + k * 128 + moff);
#pragma unroll
            for (int i = 0; i < 8; i++) {
                const unsigned long long yv = ysD[k * ZBT + tg + 8 * i];
                acc[i][0] = ffma2(yv, wv.x, acc[i][0]);
                acc[i][1] = ffma2(yv, wv.y, acc[i][1]);
            }
        }
        __syncthreads();
    }
#pragma unroll
    for (int i = 0; i < 8; i++) {
        ulonglong2 o; o.x = acc[i][0]; o.y = acc[i][1];
        *(ulonglong2*)(g_z + ((size_t)b * Tn + t0 + tg + 8 * i) * FDn + moff) = o;
    }
}

// ---------------------------------------------------------------------------
// M1: res + mix. 1024 threads, TT=64 t per block, grid 128 = one wave.
// yc table in SMEM at stride 10 (40B rows, 8B-aligned vector gathers).
// Patch indices read directly from global (L1/L2-cached, no smem staging).
// smem floats: syc 40960 | sWB 64*81 | sWpre 4096 | sres 4096  => 217344 B
// ---------------------------------------------------------------------------
#define M1_SMEM_BYTES ((Tn*10 + Pn*81 + Pn*Pn + TT*Pn) * 4)

__global__ void __launch_bounds__(1024)
resmix_kernel(const float* __restrict__ WBASE,
              const float* __restrict__ WBIAS,
              const float* __restrict__ Wpre,
              const int*   __restrict__ patches) {
    extern __shared__ __align__(16) float sm[];
    float* syc   = sm;                        // [4096][10]
    float* sWB   = syc + Tn * 10;             // [64][81]
    float* sWpre = sWB + Pn * 81;             // [64][64]
    float* sres  = sWpre + Pn * Pn;           // [64][64]

    const int b   = blockIdx.y;
    const int t0  = blockIdx.x * TT;
    const int tid = threadIdx.x;

    // ---- stage tables ----
    {
        const float* src = g_yc + (size_t)b * Tn * CSn;
        for (int i = tid; i < Tn * CSn; i += 1024)
            syc[(i / 5) * 10 + (i % 5)] = src[i];
    }
    for (int i = tid; i < Pn * PSn * CSn; i += 1024)
        sWB[(i / 80) * 81 + (i % 80)] = WBASE[i];
    if (tid < (Pn * Pn) / 4)
        ((float4*)sWpre)[tid] = ((const float4*)Wpre)[tid];
    __syncthreads();

    // ---- res: thread = (p = tid&63, tl = tid>>6 in 0..15), 4 passes ----
    const int p  = tid & 63;
    const int tl = tid >> 6;
    const float bias = __ldg(WBIAS + p);
    const float* wb = sWB + p * 81;
#pragma unroll
    for (int c4 = 0; c4 < 4; c4++) {
        const int t = t0 + c4 * 16 + tl;
        const int4* pat = (const int4*)(patches + (size_t)t * (Pn * PSn) + p * PSn);
        const int4 i0 = __ldg(pat + 0);
        const int4 i1 = __ldg(pat + 1);
        const int4 i2 = __ldg(pat + 2);
        const int4 i3 = __ldg(pat + 3);
        int idx[16] = { i0.x, i0.y, i0.z, i0.w,  i1.x, i1.y, i1.z, i1.w,
                        i2.x, i2.y, i2.z, i2.w,  i3.x, i3.y, i3.z, i3.w };
        float acc = 0.f;
#pragma unroll
        for (int s = 0; s < PSn; s++) {
            const float* yr = syc + idx[s] * 10;
            const float2 v01 = *(const float2*)yr;
            const float2 v23 = *(const float2*)(yr + 2);
            const float  v4  = yr[4];
            const float* w = wb + s * CSn;
            acc += v01.x * w[0] + v01.y * w[1] + v23.x * w[2]
                 + v23.y * w[3] + v4 * w[4];
        }
        sres[(c4 * 16 + tl) * Pn + p] = acc + bias;
    }
    __syncthreads();

    // ---- mix: q = tid&63, tg = tid>>6 handles t in {tg + 16j} ----
    {
        const int q  = tid & 63;
        const int tg = tid >> 6;
        float acc[4] = {0.f, 0.f, 0.f, 0.f};
#pragma unroll 8
        for (int pp = 0; pp < Pn; pp++) {
            const float w = sWpre[pp * Pn + q];
#pragma unroll
            for (int j = 0; j < 4; j++)
                acc[j] += sres[(tg + 16 * j) * Pn + pp] * w;
        }
#pragma unroll
        for (int j = 0; j < 4; j++)
            g_mix[((size_t)b * Tn + t0 + tg + 16 * j) * Pn + q] = acc[j];
    }
}

// ---------------------------------------------------------------------------
// M2: out[b,t,f] = sum_p mix[b,t,p] * z[b, pproj[t,p], f]
// ---------------------------------------------------------------------------
__global__ void __launch_bounds__(256)
final_kernel(const int* __restrict__ pproj, float* __restrict__ out) {
    __shared__ float smix[FT * Pn];
    __shared__ int   spp[FT * Pn];
    const int b   = blockIdx.y;
    const int t0  = blockIdx.x * FT;
    const int tid = threadIdx.x;

    {
        const float4* ms = (const float4*)(g_mix + ((size_t)b * Tn + t0) * Pn);
        ((float4*)smix)[tid] = ms[tid];
        const int4* ps = (const int4*)(pproj + (size_t)t0 * Pn);
        ((int4*)spp)[tid] = ps[tid];
    }
    __syncthreads();

    const int lane = tid & 31;
    const int th   = tid >> 5;
    const float4* zb = (const float4*)(g_z + (size_t)b * Tn * FDn) + lane;
#pragma unroll
    for (int j = 0; j < 2; j++) {
        const int tt = th * 2 + j;
        const float* mx = smix + tt * Pn;
        const int*   pr = spp + tt * Pn;
        float4 a0 = {0,0,0,0}, a1 = {0,0,0,0}, a2 = {0,0,0,0}, a3 = {0,0,0,0};
#pragma unroll
        for (int p4 = 0; p4 < Pn; p4 += 4) {
            const float4 v0 = __ldg(zb + (size_t)pr[p4 + 0] * 32);
            const float4 v1 = __ldg(zb + (size_t)pr[p4 + 1] * 32);
            const float4 v2 = __ldg(zb + (size_t)pr[p4 + 2] * 32);
            const float4 v3 = __ldg(zb + (size_t)pr[p4 + 3] * 32);
            const float m0 = mx[p4 + 0], m1 = mx[p4 + 1];
            const float m2 = mx[p4 + 2], m3 = mx[p4 + 3];
            a0.x += m0 * v0.x; a0.y += m0 * v0.y; a0.z += m0 * v0.z; a0.w += m0 * v0.w;
            a1.x += m1 * v1.x; a1.y += m1 * v1.y; a1.z += m1 * v1.z; a1.w += m1 * v1.w;
            a2.x += m2 * v2.x; a2.y += m2 * v2.y; a2.z += m2 * v2.z; a2.w += m2 * v2.w;
            a3.x += m3 * v3.x; a3.y += m3 * v3.y; a3.z += m3 * v3.z; a3.w += m3 * v3.w;
        }
        float4 o;
        o.x = (a0.x + a1.x) + (a2.x + a3.x);
        o.y = (a0.y + a1.y) + (a2.y + a3.y);
        o.z = (a0.z + a1.z) + (a2.z + a3.z);
        o.w = (a0.w + a1.w) + (a2.w + a3.w);
        ((float4*)(out + ((size_t)b * Tn + t0 + tt) * FDn))[lane] = o;
    }
}

// ---------------------------------------------------------------------------
extern "C" void kernel_launch(void* const* d_in, const int* in_sizes, int n_in,
                              void* d_out, int out_size) {
    const float* y     = (const float*)d_in[0];
    const float* WBASE = (const float*)d_in[1];
    const float* WBIAS = (const float*)d_in[2];
    const float* Wp2   = (const float*)d_in[3];
    const float* Wpc   = (const float*)d_in[4];
    const float* Wpre  = (const float*)d_in[5];
    const float* Wfin  = (const float*)d_in[6];
    const int*   patches = (const int*)d_in[7];
    const int*   pproj   = (const int*)d_in[8];
    float* out = (float*)d_out;

    cudaFuncSetAttribute(resmix_kernel,
                         cudaFuncAttributeMaxDynamicSharedMemorySize,
                         M1_SMEM_BYTES);

    wcomb_kernel<<<128, 128>>>(Wp2, Wfin);
    yc_kernel<<<dim3(Tn / 64, Bn), 256>>>(y, Wpc);
    z_kernel<<<dim3(Tn / ZBT, Bn), 256>>>(y);
    resmix_kernel<<<dim3(Tn / TT, Bn), 1024, M1_SMEM_BYTES>>>(
        WBASE, WBIAS, Wpre, patches);
    final_kernel<<<dim3(Tn / FT, Bn), 256>>>(pproj, out);
}